// round 7
// baseline (speedup 1.0000x reference)
#include <cuda_runtime.h>
#include <math.h>

// Problem constants
#define NL   2
#define Dm   512
#define Ns   16
#define Bb   4
#define Ls   2048
#define Cc   8            // scan chunks
#define Lc   (Ls/Cc)      // 256 steps per chunk
#define BLD  (Bb*Ls*Dm)   // 4,194,304
#define BLN  (Bb*Ls*Ns)   // 131,072
#define BDN  (Bb*Dm*Ns)   // 32,768

// Scratch (no allocations allowed -> device globals)
__device__ float g_h [BLD];   // current layer activations
__device__ float g_dt[BLD];   // dt buffer, reused as mix-GEMM output z
__device__ float g_y [BLD];   // scan output (GELU applied in scan3)
__device__ float g_Bm[BLN];
__device__ float g_Cm[BLN];
__device__ float g_cA[Cc*BDN];
__device__ float g_cH[Cc*BDN];

// ---------------------------------------------------------------------------
// Tiled fp32 GEMM: C[M,Nn] = A[M,K] @ B[K,Nn] + bias, optional softplus.
// BM=BN=128, BK=16, 256 threads, 8x8 per thread, double-buffered smem with
// register prefetch; ONE __syncthreads per k-tile (32 total for K=512).
// __launch_bounds__(256,2): cap regs at 128 so 2 CTAs co-reside per SM
// (32 KB smem each) and cross-CTA overlap hides the per-tile barrier drain.
// Epilogue uses float4 stores (16x STG.128 instead of 64x STG.32).
// epi: 0 = bias, 1 = softplus(v + bias)
// ---------------------------------------------------------------------------
__global__ __launch_bounds__(256, 2) void sgemm128(
    const float* __restrict__ A, const float* __restrict__ Bw,
    const float* __restrict__ bias, float* __restrict__ Cout,
    int K, int Nn, int epi)
{
    __shared__ float As[2][16][128];   // [k][m], A stored transposed
    __shared__ float Bs[2][16][128];   // [k][n]

    const int bm = blockIdx.y, bn = blockIdx.x;
    const int t  = threadIdx.x;

    // A tile 128x16 = 512 float4 slots; thread handles rows arow and arow+64
    const int arow = t >> 2;             // 0..63
    const int acol = (t & 3) * 4;        // 0,4,8,12
    // B tile 16x128 = 512 float4 slots; thread handles rows brow and brow+8
    const int brow = t >> 5;             // 0..7
    const int bcol = (t & 31) * 4;       // 0..124

    const float* Ap = A  + (size_t)(bm * 128) * K;
    const float* Bp = Bw + bn * 128;

    const int rm = (t >> 4) * 8;
    const int rn = (t & 15) * 8;

    float acc[8][8];
#pragma unroll
    for (int i = 0; i < 8; i++)
#pragma unroll
        for (int j = 0; j < 8; j++) acc[i][j] = 0.f;

    // prefetch first k-tile into registers (4 independent LDG.128)
    float4 av0 = *(const float4*)(Ap + (size_t)arow        * K + acol);
    float4 av1 = *(const float4*)(Ap + (size_t)(arow + 64) * K + acol);
    float4 bv0 = *(const float4*)(Bp + (size_t)brow       * Nn + bcol);
    float4 bv1 = *(const float4*)(Bp + (size_t)(brow + 8) * Nn + bcol);

    int buf = 0;
    for (int k0 = 0; k0 < K; k0 += 16) {
        // commit current tile to smem
        As[buf][acol + 0][arow]      = av0.x;
        As[buf][acol + 1][arow]      = av0.y;
        As[buf][acol + 2][arow]      = av0.z;
        As[buf][acol + 3][arow]      = av0.w;
        As[buf][acol + 0][arow + 64] = av1.x;
        As[buf][acol + 1][arow + 64] = av1.y;
        As[buf][acol + 2][arow + 64] = av1.z;
        As[buf][acol + 3][arow + 64] = av1.w;
        *(float4*)&Bs[buf][brow][bcol]     = bv0;
        *(float4*)&Bs[buf][brow + 8][bcol] = bv1;
        __syncthreads();

        // issue next tile's global loads (overlap with compute below)
        if (k0 + 16 < K) {
            const int kn = k0 + 16;
            av0 = *(const float4*)(Ap + (size_t)arow        * K + kn + acol);
            av1 = *(const float4*)(Ap + (size_t)(arow + 64) * K + kn + acol);
            bv0 = *(const float4*)(Bp + (size_t)(kn + brow)     * Nn + bcol);
            bv1 = *(const float4*)(Bp + (size_t)(kn + brow + 8) * Nn + bcol);
        }

#pragma unroll
        for (int kk = 0; kk < 16; kk++) {
            float af[8], bf[8];
            *(float4*)&af[0] = *(const float4*)&As[buf][kk][rm];
            *(float4*)&af[4] = *(const float4*)&As[buf][kk][rm + 4];
            *(float4*)&bf[0] = *(const float4*)&Bs[buf][kk][rn];
            *(float4*)&bf[4] = *(const float4*)&Bs[buf][kk][rn + 4];
#pragma unroll
            for (int i = 0; i < 8; i++)
#pragma unroll
                for (int j = 0; j < 8; j++)
                    acc[i][j] = fmaf(af[i], bf[j], acc[i][j]);
        }
        buf ^= 1;
        // no second sync: next store targets the other buffer; the next
        // iteration's sync orders reuse of this one.
    }

    // epilogue: bias (+ optional softplus), vectorized float4 stores
    const float4 bg0 = *(const float4*)(bias + bn * 128 + rn);
    const float4 bg1 = *(const float4*)(bias + bn * 128 + rn + 4);
#pragma unroll
    for (int i = 0; i < 8; i++) {
        const int row = bm * 128 + rm + i;
        float v[8];
        v[0] = acc[i][0] + bg0.x;  v[1] = acc[i][1] + bg0.y;
        v[2] = acc[i][2] + bg0.z;  v[3] = acc[i][3] + bg0.w;
        v[4] = acc[i][4] + bg1.x;  v[5] = acc[i][5] + bg1.y;
        v[6] = acc[i][6] + bg1.z;  v[7] = acc[i][7] + bg1.w;
        if (epi == 1) {  // softplus, numerically stable
#pragma unroll
            for (int j = 0; j < 8; j++)
                v[j] = (v[j] > 20.f) ? v[j] : log1pf(__expf(v[j]));
        }
        float* cp = Cout + (size_t)row * Nn + bn * 128 + rn;
        *(float4*)(cp)     = *(float4*)&v[0];
        *(float4*)(cp + 4) = *(float4*)&v[4];
    }
}

// ---------------------------------------------------------------------------
// Bm/Cm projections: [tokens,512] @ [512,16] (+bias) for both W_B and W_C.
// Warp = 4 tokens. Lane = (token-group g = lane>>3) x (B/C = bit2 of lane)
// x (n-quad = lane&3). x loaded as float4 (4 k per LDG), W rows as float4
// (4 n per LDG): per 4 k-steps a warp issues 1+4 LDG.128 + 16 FFMA covering
// 4 tokens, vs 32 LDG + 16 FFMA in the scalar version.
// ---------------------------------------------------------------------------
__global__ __launch_bounds__(256) void bc_gemm(
    const float* __restrict__ Wb, const float* __restrict__ bb,
    const float* __restrict__ Wc, const float* __restrict__ bc_)
{
    const int t    = threadIdx.x;
    const int lane = t & 31;
    const int wid  = t >> 5;                    // 0..7
    const int g    = lane >> 3;                 // token group 0..3
    const int sub  = lane & 7;
    const bool isC = sub >= 4;
    const int nq   = (sub & 3) * 4;             // n base: 0,4,8,12
    const int token = (blockIdx.x * 8 + wid) * 4 + g;

    const float* W  = isC ? Wc : Wb;            // [512][16] row-major
    const float* xr = g_h + (size_t)token * Dm;

    float4 acc = make_float4(0.f, 0.f, 0.f, 0.f);
#pragma unroll 2
    for (int k = 0; k < Dm; k += 4) {
        const float4 xv = *(const float4*)(xr + k);
        float4 w;
        w = *(const float4*)(W + (size_t)(k + 0) * Ns + nq);
        acc.x = fmaf(xv.x, w.x, acc.x); acc.y = fmaf(xv.x, w.y, acc.y);
        acc.z = fmaf(xv.x, w.z, acc.z); acc.w = fmaf(xv.x, w.w, acc.w);
        w = *(const float4*)(W + (size_t)(k + 1) * Ns + nq);
        acc.x = fmaf(xv.y, w.x, acc.x); acc.y = fmaf(xv.y, w.y, acc.y);
        acc.z = fmaf(xv.y, w.z, acc.z); acc.w = fmaf(xv.y, w.w, acc.w);
        w = *(const float4*)(W + (size_t)(k + 2) * Ns + nq);
        acc.x = fmaf(xv.z, w.x, acc.x); acc.y = fmaf(xv.z, w.y, acc.y);
        acc.z = fmaf(xv.z, w.z, acc.z); acc.w = fmaf(xv.z, w.w, acc.w);
        w = *(const float4*)(W + (size_t)(k + 3) * Ns + nq);
        acc.x = fmaf(xv.w, w.x, acc.x); acc.y = fmaf(xv.w, w.y, acc.y);
        acc.z = fmaf(xv.w, w.z, acc.z); acc.w = fmaf(xv.w, w.w, acc.w);
    }

    const float4 bv = *(const float4*)((isC ? bc_ : bb) + nq);
    acc.x += bv.x; acc.y += bv.y; acc.z += bv.z; acc.w += bv.w;

    float* dst = (isC ? g_Cm : g_Bm) + (size_t)token * Ns + nq;
    *(float4*)dst = acc;
}

// ---------------------------------------------------------------------------
// Scan pass 1: per-chunk carries. Warp lanes: [0..15] -> d0, n; [16..31] -> d0+1.
// The LAST chunk's carry is never consumed (prefixes only fold earlier
// chunks), so those warps exit immediately.
// ---------------------------------------------------------------------------
__global__ __launch_bounds__(256) void scan1(const float* __restrict__ A_log, int layer)
{
    const int t    = blockIdx.x * 256 + threadIdx.x;
    const int lane = t & 31;
    const int w    = t >> 5;
    const int c    = w & (Cc - 1);
    if (c == Cc - 1) return;   // carry of final chunk is unused
    const int d    = (((w >> 3) & 255) << 1) + (lane >> 4);
    const int b    = w >> 11;
    const int n    = lane & 15;

    const float Ac = -__expf(A_log[((size_t)layer * Dm + d) * Ns + n]);

    float h = 0.f, ap = 1.f;
    const size_t base  = ((size_t)b * Ls + c * Lc) * Dm + d;
    const size_t bbase = ((size_t)b * Ls + c * Lc) * Ns + n;

#pragma unroll 4
    for (int l = 0; l < Lc; l++) {
        const float dtv = g_dt[base + (size_t)l * Dm];
        const float xv  = g_h [base + (size_t)l * Dm];
        const float Bv  = g_Bm[bbase + (size_t)l * Ns];
        const float a   = __expf(dtv * Ac);
        h  = fmaf(a, h, dtv * xv * Bv);
        ap *= a;
    }
    const int idx = (b * Dm + d) * Ns + n;
    g_cA[c * BDN + idx] = ap;
    g_cH[c * BDN + idx] = h;
}

// ---------------------------------------------------------------------------
// Scan pass 3: fold incoming prefix from chunk carries (<= 7 fmas, replaces
// the old scan2 launch), replay chunk with prefix, fuse y = C.h + D_skip*x
// (16-lane shfl reduce) and the exact-erf GELU at the single write point.
// ---------------------------------------------------------------------------
__global__ __launch_bounds__(256) void scan3(
    const float* __restrict__ A_log, const float* __restrict__ Dsk, int layer)
{
    const int t    = blockIdx.x * 256 + threadIdx.x;
    const int lane = t & 31;
    const int w    = t >> 5;
    const int c    = w & (Cc - 1);
    const int d    = (((w >> 3) & 255) << 1) + (lane >> 4);
    const int b    = w >> 11;
    const int n    = lane & 15;

    const float Ac = -__expf(A_log[((size_t)layer * Dm + d) * Ns + n]);
    const float Dv = Dsk[layer * Dm + d];

    const int idx = (b * Dm + d) * Ns + n;

    // incoming prefix: fold carries of chunks 0..c-1 (scan2's loop, local)
    float h = 0.f;
    for (int cp = 0; cp < c; cp++)
        h = fmaf(g_cA[cp * BDN + idx], h, g_cH[cp * BDN + idx]);

    const size_t base  = ((size_t)b * Ls + c * Lc) * Dm + d;
    const size_t bbase = ((size_t)b * Ls + c * Lc) * Ns + n;

#pragma unroll 4
    for (int l = 0; l < Lc; l++) {
        const float dtv = g_dt[base + (size_t)l * Dm];
        const float xv  = g_h [base + (size_t)l * Dm];
        const float Bv  = g_Bm[bbase + (size_t)l * Ns];
        const float Cv  = g_Cm[bbase + (size_t)l * Ns];
        const float a   = __expf(dtv * Ac);
        h = fmaf(a, h, dtv * xv * Bv);
        float p = Cv * h;
        p += __shfl_xor_sync(0xffffffffu, p, 8);
        p += __shfl_xor_sync(0xffffffffu, p, 4);
        p += __shfl_xor_sync(0xffffffffu, p, 2);
        p += __shfl_xor_sync(0xffffffffu, p, 1);
        if (n == 0) {
            const float yv = fmaf(Dv, xv, p);
            // exact-erf GELU fused at the single write point
            g_y[base + (size_t)l * Dm] =
                0.5f * yv * (1.f + erff(yv * 0.70710678118654752f));
        }
    }
}

// ---------------------------------------------------------------------------
// LayerNorm(z) * g + b, residual into g_h. One warp per token, z in g_dt.
// ---------------------------------------------------------------------------
__global__ __launch_bounds__(256) void ln_res(
    const float* __restrict__ gam, const float* __restrict__ bet, int layer)
{
    const int gt   = blockIdx.x * 256 + threadIdx.x;
    const int w    = gt >> 5;        // token
    const int lane = gt & 31;
    const float* z = g_dt + (size_t)w * Dm;

    float v[16];
    float s = 0.f, s2 = 0.f;
#pragma unroll
    for (int i = 0; i < 16; i++) {
        v[i] = z[lane + i * 32];
        s  += v[i];
        s2 += v[i] * v[i];
    }
#pragma unroll
    for (int o = 16; o >= 1; o >>= 1) {
        s  += __shfl_xor_sync(0xffffffffu, s,  o);
        s2 += __shfl_xor_sync(0xffffffffu, s2, o);
    }
    const float mu  = s * (1.f / Dm);
    const float var = s2 * (1.f / Dm) - mu * mu;
    const float inv = rsqrtf(var + 1e-5f);

#pragma unroll
    for (int i = 0; i < 16; i++) {
        const int dcol = lane + i * 32;
        const float nv = (v[i] - mu) * inv * gam[layer * Dm + dcol] + bet[layer * Dm + dcol];
        g_h[(size_t)w * Dm + dcol] += nv;
    }
}

// ---------------------------------------------------------------------------
extern "C" void kernel_launch(void* const* d_in, const int* in_sizes, int n_in,
                              void* d_out, int out_size)
{
    const float* x      = (const float*)d_in[0];
    const float* A_log  = (const float*)d_in[1];
    const float* W_B    = (const float*)d_in[2];
    const float* b_B    = (const float*)d_in[3];
    const float* W_C    = (const float*)d_in[4];
    const float* b_C    = (const float*)d_in[5];
    const float* W_dt   = (const float*)d_in[6];
    const float* b_dt   = (const float*)d_in[7];
    const float* D_skip = (const float*)d_in[8];
    const float* W_mix  = (const float*)d_in[9];
    const float* b_mix  = (const float*)d_in[10];
    const float* ln_g   = (const float*)d_in[11];
    const float* ln_b   = (const float*)d_in[12];
    const float* W_dec  = (const float*)d_in[13];
    const float* b_dec  = (const float*)d_in[14];
    float* out = (float*)d_out;

    float *p_h, *p_dt, *p_y;
    cudaGetSymbolAddress((void**)&p_h,  g_h);
    cudaGetSymbolAddress((void**)&p_dt, g_dt);
    cudaGetSymbolAddress((void**)&p_y,  g_y);

    cudaMemcpyAsync(p_h, x, sizeof(float) * BLD, cudaMemcpyDeviceToDevice);

    const dim3 gg(Dm / 128, (Bb * Ls) / 128);  // (4, 64)

    for (int i = 0; i < NL; i++) {
        // dt = softplus(h @ W_dt + b_dt)
        sgemm128<<<gg, 256>>>(p_h, W_dt + (size_t)i * Dm * Dm, b_dt + i * Dm,
                              p_dt, Dm, Dm, 1);
        // Bm, Cm (8192 tokens / 32 per block = 256 blocks)
        bc_gemm<<<256, 256>>>(W_B + (size_t)i * Dm * Ns, b_B + i * Ns,
                              W_C + (size_t)i * Dm * Ns, b_C + i * Ns);
        // chunked associative scan + y (+ fused prefix fold and GELU)
        scan1<<<(Bb * (Dm / 2) * Cc * 32) / 256, 256>>>(A_log, i);
        scan3<<<(Bb * (Dm / 2) * Cc * 32) / 256, 256>>>(A_log, D_skip, i);
        // z = gelu(y) @ W_mix + b_mix  (into g_dt, dt no longer needed)
        sgemm128<<<gg, 256>>>(p_y, W_mix + (size_t)i * Dm * Dm, b_mix + i * Dm,
                              p_dt, Dm, Dm, 0);
        // h = h + LN(z)*g + b
        ln_res<<<(Bb * Ls * 32) / 256, 256>>>(ln_g, ln_b, i);
    }

    // out = h @ W_dec + b_dec
    sgemm128<<<gg, 256>>>(p_h, W_dec, b_dec, out, Dm, Dm, 0);
}

// round 14
// speedup vs baseline: 1.2255x; 1.2255x over previous
#include <cuda_runtime.h>
#include <math.h>

// Problem constants
#define NL   2
#define Dm   512
#define Ns   16
#define Bb   4
#define Ls   2048
#define Cc   32           // scan chunks
#define Lc   (Ls/Cc)      // 64 steps per chunk
#define BLD  (Bb*Ls*Dm)   // 4,194,304
#define BLN  (Bb*Ls*Ns)   // 131,072
#define BDN  (Bb*Dm*Ns)   // 32,768
#define LOG2E 1.4426950408889634f

// Scratch (no allocations allowed -> device globals)
__device__ float g_h [BLD];   // current layer activations
__device__ float g_dt[BLD];   // dt buffer, reused as mix-GEMM output z
__device__ float g_y [BLD];   // scan output (GELU applied in scan3)
__device__ float g_Bm[BLN];
__device__ float g_Cm[BLN];
__device__ float g_cA[Cc*BDN];
__device__ float g_cH[Cc*BDN];
__device__ float g_pH[Cc*BDN];

__device__ __forceinline__ float ex2(float x) {
    float r;
    asm("ex2.approx.f32 %0, %1;" : "=f"(r) : "f"(x));
    return r;
}

// ---------------------------------------------------------------------------
// Tiled fp32 GEMM: C[M,512] = A[M,512] @ B[512,512] + bias, opt. softplus.
// K and Nn are compile-time (512): strides fold to immediate offsets.
// BM=BN=128, BK=16, 256 threads, 8x8 per thread, double-buffered smem.
// epi: 0 = bias, 1 = softplus(v + bias)
// ---------------------------------------------------------------------------
#define GK 512
#define GN 512
__global__ __launch_bounds__(256, 2) void sgemm128(
    const float* __restrict__ A, const float* __restrict__ Bw,
    const float* __restrict__ bias, float* __restrict__ Cout, int epi)
{
    __shared__ float As[2][16][128];   // [k][m], A stored transposed
    __shared__ float Bs[2][16][128];   // [k][n]

    const int bm = blockIdx.y, bn = blockIdx.x;
    const int t  = threadIdx.x;

    const int arow = t >> 2;             // 0..63
    const int acol = (t & 3) * 4;        // 0,4,8,12
    const int brow = t >> 5;             // 0..7
    const int bcol = (t & 31) * 4;       // 0..124

    const float* Ap = A  + (size_t)(bm * 128) * GK;
    const float* Bp = Bw + bn * 128;

    const int rm = (t >> 4) * 8;
    const int rn = (t & 15) * 8;

    float acc[8][8];
#pragma unroll
    for (int i = 0; i < 8; i++)
#pragma unroll
        for (int j = 0; j < 8; j++) acc[i][j] = 0.f;

    float4 av0 = *(const float4*)(Ap + (size_t)arow        * GK + acol);
    float4 av1 = *(const float4*)(Ap + (size_t)(arow + 64) * GK + acol);
    float4 bv0 = *(const float4*)(Bp + (size_t)brow       * GN + bcol);
    float4 bv1 = *(const float4*)(Bp + (size_t)(brow + 8) * GN + bcol);

    int buf = 0;
    for (int k0 = 0; k0 < GK; k0 += 16) {
        As[buf][acol + 0][arow]      = av0.x;
        As[buf][acol + 1][arow]      = av0.y;
        As[buf][acol + 2][arow]      = av0.z;
        As[buf][acol + 3][arow]      = av0.w;
        As[buf][acol + 0][arow + 64] = av1.x;
        As[buf][acol + 1][arow + 64] = av1.y;
        As[buf][acol + 2][arow + 64] = av1.z;
        As[buf][acol + 3][arow + 64] = av1.w;
        *(float4*)&Bs[buf][brow][bcol]     = bv0;
        *(float4*)&Bs[buf][brow + 8][bcol] = bv1;
        __syncthreads();

        if (k0 + 16 < GK) {
            const int kn = k0 + 16;
            av0 = *(const float4*)(Ap + (size_t)arow        * GK + kn + acol);
            av1 = *(const float4*)(Ap + (size_t)(arow + 64) * GK + kn + acol);
            bv0 = *(const float4*)(Bp + (size_t)(kn + brow)     * GN + bcol);
            bv1 = *(const float4*)(Bp + (size_t)(kn + brow + 8) * GN + bcol);
        }

#pragma unroll
        for (int kk = 0; kk < 16; kk++) {
            float af[8], bf[8];
            *(float4*)&af[0] = *(const float4*)&As[buf][kk][rm];
            *(float4*)&af[4] = *(const float4*)&As[buf][kk][rm + 4];
            *(float4*)&bf[0] = *(const float4*)&Bs[buf][kk][rn];
            *(float4*)&bf[4] = *(const float4*)&Bs[buf][kk][rn + 4];
#pragma unroll
            for (int i = 0; i < 8; i++)
#pragma unroll
                for (int j = 0; j < 8; j++)
                    acc[i][j] = fmaf(af[i], bf[j], acc[i][j]);
        }
        buf ^= 1;
    }

    const float4 bg0 = *(const float4*)(bias + bn * 128 + rn);
    const float4 bg1 = *(const float4*)(bias + bn * 128 + rn + 4);
#pragma unroll
    for (int i = 0; i < 8; i++) {
        const int row = bm * 128 + rm + i;
        float v[8];
        v[0] = acc[i][0] + bg0.x;  v[1] = acc[i][1] + bg0.y;
        v[2] = acc[i][2] + bg0.z;  v[3] = acc[i][3] + bg0.w;
        v[4] = acc[i][4] + bg1.x;  v[5] = acc[i][5] + bg1.y;
        v[6] = acc[i][6] + bg1.z;  v[7] = acc[i][7] + bg1.w;
        if (epi == 1) {
#pragma unroll
            for (int j = 0; j < 8; j++)
                v[j] = (v[j] > 20.f) ? v[j] : log1pf(__expf(v[j]));
        }
        float* cp = Cout + (size_t)row * GN + bn * 128 + rn;
        *(float4*)(cp)     = *(float4*)&v[0];
        *(float4*)(cp + 4) = *(float4*)&v[4];
    }
}

// ---------------------------------------------------------------------------
// Bm/Cm projections (float4-vectorized over k and n).
// ---------------------------------------------------------------------------
__global__ __launch_bounds__(256) void bc_gemm(
    const float* __restrict__ Wb, const float* __restrict__ bb,
    const float* __restrict__ Wc, const float* __restrict__ bc_)
{
    const int t    = threadIdx.x;
    const int lane = t & 31;
    const int wid  = t >> 5;
    const int g    = lane >> 3;
    const int sub  = lane & 7;
    const bool isC = sub >= 4;
    const int nq   = (sub & 3) * 4;
    const int token = (blockIdx.x * 8 + wid) * 4 + g;

    const float* W  = isC ? Wc : Wb;
    const float* xr = g_h + (size_t)token * Dm;

    float4 acc = make_float4(0.f, 0.f, 0.f, 0.f);
#pragma unroll 2
    for (int k = 0; k < Dm; k += 4) {
        const float4 xv = *(const float4*)(xr + k);
        float4 w;
        w = *(const float4*)(W + (size_t)(k + 0) * Ns + nq);
        acc.x = fmaf(xv.x, w.x, acc.x); acc.y = fmaf(xv.x, w.y, acc.y);
        acc.z = fmaf(xv.x, w.z, acc.z); acc.w = fmaf(xv.x, w.w, acc.w);
        w = *(const float4*)(W + (size_t)(k + 1) * Ns + nq);
        acc.x = fmaf(xv.y, w.x, acc.x); acc.y = fmaf(xv.y, w.y, acc.y);
        acc.z = fmaf(xv.y, w.z, acc.z); acc.w = fmaf(xv.y, w.w, acc.w);
        w = *(const float4*)(W + (size_t)(k + 2) * Ns + nq);
        acc.x = fmaf(xv.z, w.x, acc.x); acc.y = fmaf(xv.z, w.y, acc.y);
        acc.z = fmaf(xv.z, w.z, acc.z); acc.w = fmaf(xv.z, w.w, acc.w);
        w = *(const float4*)(W + (size_t)(k + 3) * Ns + nq);
        acc.x = fmaf(xv.w, w.x, acc.x); acc.y = fmaf(xv.w, w.y, acc.y);
        acc.z = fmaf(xv.w, w.z, acc.z); acc.w = fmaf(xv.w, w.w, acc.w);
    }

    const float4 bv = *(const float4*)((isC ? bc_ : bb) + nq);
    acc.x += bv.x; acc.y += bv.y; acc.z += bv.z; acc.w += bv.w;

    float* dst = (isC ? g_Cm : g_Bm) + (size_t)token * Ns + nq;
    *(float4*)dst = acc;
}

// Per-n update macro for one float4 group: e = 2^(dt*Ac2), h = e*h + dtx*B
#define SCAN_UPD(hh, aa, BB) \
    ex = ex2(dtv * aa.x); hh.x = fmaf(ex, hh.x, dtx * BB.x); \
    ey = ex2(dtv * aa.y); hh.y = fmaf(ey, hh.y, dtx * BB.y); \
    ez = ex2(dtv * aa.z); hh.z = fmaf(ez, hh.z, dtx * BB.z); \
    ew = ex2(dtv * aa.w); hh.w = fmaf(ew, hh.w, dtx * BB.w);

// ---------------------------------------------------------------------------
// Scan pass 1: per-chunk carries. ONE THREAD owns (b, d, chunk) and all 16
// n-states in registers (4 float4 chains). Lanes span consecutive d, so
// dt/x loads are coalesced and each element is loaded once (not 16x).
// Chunks 0..Cc-2 only (last chunk's carry is never consumed).
// ---------------------------------------------------------------------------
__global__ __launch_bounds__(256) void scan1(const float* __restrict__ A_log, int layer)
{
    const int tid = blockIdx.x * 256 + threadIdx.x;   // < 31*2048
    const int c   = tid >> 11;          // 0..30
    const int r   = tid & 2047;
    const int b   = r >> 9;
    const int d   = r & 511;

    const float4* Ar = (const float4*)(A_log + ((size_t)layer * Dm + d) * Ns);
    float4 a0 = Ar[0], a1 = Ar[1], a2 = Ar[2], a3 = Ar[3];
    a0.x = -__expf(a0.x) * LOG2E; a0.y = -__expf(a0.y) * LOG2E;
    a0.z = -__expf(a0.z) * LOG2E; a0.w = -__expf(a0.w) * LOG2E;
    a1.x = -__expf(a1.x) * LOG2E; a1.y = -__expf(a1.y) * LOG2E;
    a1.z = -__expf(a1.z) * LOG2E; a1.w = -__expf(a1.w) * LOG2E;
    a2.x = -__expf(a2.x) * LOG2E; a2.y = -__expf(a2.y) * LOG2E;
    a2.z = -__expf(a2.z) * LOG2E; a2.w = -__expf(a2.w) * LOG2E;
    a3.x = -__expf(a3.x) * LOG2E; a3.y = -__expf(a3.y) * LOG2E;
    a3.z = -__expf(a3.z) * LOG2E; a3.w = -__expf(a3.w) * LOG2E;

    float4 h0 = {0,0,0,0}, h1 = {0,0,0,0}, h2 = {0,0,0,0}, h3 = {0,0,0,0};
    float4 q0 = {1,1,1,1}, q1 = {1,1,1,1}, q2 = {1,1,1,1}, q3 = {1,1,1,1};

    const size_t base  = ((size_t)b * Ls + c * Lc) * Dm + d;
    const size_t bbase = ((size_t)b * Ls + c * Lc) * Ns;

#pragma unroll 2
    for (int l = 0; l < Lc; l++) {
        const float dtv = g_dt[base + (size_t)l * Dm];
        const float xv  = g_h [base + (size_t)l * Dm];
        const float4* Br = (const float4*)(g_Bm + bbase + (size_t)l * Ns);
        const float4 B0 = Br[0], B1 = Br[1], B2 = Br[2], B3 = Br[3];
        const float dtx = dtv * xv;
        float ex, ey, ez, ew;
        SCAN_UPD(h0, a0, B0); q0.x *= ex; q0.y *= ey; q0.z *= ez; q0.w *= ew;
        SCAN_UPD(h1, a1, B1); q1.x *= ex; q1.y *= ey; q1.z *= ez; q1.w *= ew;
        SCAN_UPD(h2, a2, B2); q2.x *= ex; q2.y *= ey; q2.z *= ez; q2.w *= ew;
        SCAN_UPD(h3, a3, B3); q3.x *= ex; q3.y *= ey; q3.z *= ez; q3.w *= ew;
    }

    const size_t idx = (size_t)c * BDN + ((size_t)(b * Dm + d)) * Ns;
    float4* pa = (float4*)(g_cA + idx);
    float4* ph = (float4*)(g_cH + idx);
    pa[0] = q0; pa[1] = q1; pa[2] = q2; pa[3] = q3;
    ph[0] = h0; ph[1] = h1; ph[2] = h2; ph[3] = h3;
}

// ---------------------------------------------------------------------------
// Scan pass 2: exclusive scan of chunk carries, float4 over n (4 states/thread).
// ---------------------------------------------------------------------------
__global__ void scan2()
{
    const int q = blockIdx.x * blockDim.x + threadIdx.x;  // [0, BDN/4)
    float4 h = {0.f, 0.f, 0.f, 0.f};
#pragma unroll
    for (int c = 0; c < Cc; c++) {
        ((float4*)g_pH)[c * (BDN / 4) + q] = h;
        if (c < Cc - 1) {
            const float4 a = ((const float4*)g_cA)[c * (BDN / 4) + q];
            const float4 u = ((const float4*)g_cH)[c * (BDN / 4) + q];
            h.x = fmaf(a.x, h.x, u.x);
            h.y = fmaf(a.y, h.y, u.y);
            h.z = fmaf(a.z, h.z, u.z);
            h.w = fmaf(a.w, h.w, u.w);
        }
    }
}

// ---------------------------------------------------------------------------
// Scan pass 3: replay chunk with incoming prefix; 16 n-states in registers;
// y = sum_n C*h + D_skip*x computed in-thread (no shuffles); exact-erf GELU
// fused at the single coalesced write.
// ---------------------------------------------------------------------------
__global__ __launch_bounds__(256) void scan3(
    const float* __restrict__ A_log, const float* __restrict__ Dsk, int layer)
{
    const int tid = blockIdx.x * 256 + threadIdx.x;   // < 32*2048
    const int c   = tid >> 11;          // 0..31
    const int r   = tid & 2047;
    const int b   = r >> 9;
    const int d   = r & 511;

    const float4* Ar = (const float4*)(A_log + ((size_t)layer * Dm + d) * Ns);
    float4 a0 = Ar[0], a1 = Ar[1], a2 = Ar[2], a3 = Ar[3];
    a0.x = -__expf(a0.x) * LOG2E; a0.y = -__expf(a0.y) * LOG2E;
    a0.z = -__expf(a0.z) * LOG2E; a0.w = -__expf(a0.w) * LOG2E;
    a1.x = -__expf(a1.x) * LOG2E; a1.y = -__expf(a1.y) * LOG2E;
    a1.z = -__expf(a1.z) * LOG2E; a1.w = -__expf(a1.w) * LOG2E;
    a2.x = -__expf(a2.x) * LOG2E; a2.y = -__expf(a2.y) * LOG2E;
    a2.z = -__expf(a2.z) * LOG2E; a2.w = -__expf(a2.w) * LOG2E;
    a3.x = -__expf(a3.x) * LOG2E; a3.y = -__expf(a3.y) * LOG2E;
    a3.z = -__expf(a3.z) * LOG2E; a3.w = -__expf(a3.w) * LOG2E;

    const float Dv = Dsk[layer * Dm + d];

    const size_t idx = (size_t)c * BDN + ((size_t)(b * Dm + d)) * Ns;
    const float4* pp = (const float4*)(g_pH + idx);
    float4 h0 = pp[0], h1 = pp[1], h2 = pp[2], h3 = pp[3];

    const size_t base  = ((size_t)b * Ls + c * Lc) * Dm + d;
    const size_t bbase = ((size_t)b * Ls + c * Lc) * Ns;

#pragma unroll 2
    for (int l = 0; l < Lc; l++) {
        const float dtv = g_dt[base + (size_t)l * Dm];
        const float xv  = g_h [base + (size_t)l * Dm];
        const float4* Br = (const float4*)(g_Bm + bbase + (size_t)l * Ns);
        const float4* Cr = (const float4*)(g_Cm + bbase + (size_t)l * Ns);
        const float4 B0 = Br[0], B1 = Br[1], B2 = Br[2], B3 = Br[3];
        const float4 C0 = Cr[0], C1 = Cr[1], C2 = Cr[2], C3 = Cr[3];
        const float dtx = dtv * xv;
        float ex, ey, ez, ew;
        float p = 0.f;
        SCAN_UPD(h0, a0, B0);
        p = fmaf(C0.x, h0.x, p); p = fmaf(C0.y, h0.y, p);
        p = fmaf(C0.z, h0.z, p); p = fmaf(C0.w, h0.w, p);
        SCAN_UPD(h1, a1, B1);
        p = fmaf(C1.x, h1.x, p); p = fmaf(C1.y, h1.y, p);
        p = fmaf(C1.z, h1.z, p); p = fmaf(C1.w, h1.w, p);
        SCAN_UPD(h2, a2, B2);
        p = fmaf(C2.x, h2.x, p); p = fmaf(C2.y, h2.y, p);
        p = fmaf(C2.z, h2.z, p); p = fmaf(C2.w, h2.w, p);
        SCAN_UPD(h3, a3, B3);
        p = fmaf(C3.x, h3.x, p); p = fmaf(C3.y, h3.y, p);
        p = fmaf(C3.z, h3.z, p); p = fmaf(C3.w, h3.w, p);

        const float yv = fmaf(Dv, xv, p);
        g_y[base + (size_t)l * Dm] =
            0.5f * yv * (1.f + erff(yv * 0.70710678118654752f));
    }
}

// ---------------------------------------------------------------------------
// LayerNorm(z) * g + b, residual into g_h. One warp per token, z in g_dt.
// float4-vectorized; full-row reduction is lane-order independent.
// ---------------------------------------------------------------------------
__global__ __launch_bounds__(256) void ln_res(
    const float* __restrict__ gam, const float* __restrict__ bet, int layer)
{
    const int gt   = blockIdx.x * 256 + threadIdx.x;
    const int w    = gt >> 5;        // token
    const int lane = gt & 31;
    const float* z = g_dt + (size_t)w * Dm;

    float4 v[4];
    float s = 0.f, s2 = 0.f;
#pragma unroll
    for (int i = 0; i < 4; i++) {
        v[i] = *(const float4*)(z + lane * 4 + i * 128);
        s  += (v[i].x + v[i].y) + (v[i].z + v[i].w);
        s2 += v[i].x * v[i].x + v[i].y * v[i].y
            + v[i].z * v[i].z + v[i].w * v[i].w;
    }
#pragma unroll
    for (int o = 16; o >= 1; o >>= 1) {
        s  += __shfl_xor_sync(0xffffffffu, s,  o);
        s2 += __shfl_xor_sync(0xffffffffu, s2, o);
    }
    const float mu  = s * (1.f / Dm);
    const float var = s2 * (1.f / Dm) - mu * mu;
    const float inv = rsqrtf(var + 1e-5f);

#pragma unroll
    for (int i = 0; i < 4; i++) {
        const int dcol = lane * 4 + i * 128;
        const float4 gv = *(const float4*)(gam + layer * Dm + dcol);
        const float4 bv = *(const float4*)(bet + layer * Dm + dcol);
        float4* hp = (float4*)(g_h + (size_t)w * Dm + dcol);
        float4 hv = *hp;
        hv.x += (v[i].x - mu) * inv * gv.x + bv.x;
        hv.y += (v[i].y - mu) * inv * gv.y + bv.y;
        hv.z += (v[i].z - mu) * inv * gv.z + bv.z;
        hv.w += (v[i].w - mu) * inv * gv.w + bv.w;
        *hp = hv;
    }
}

// ---------------------------------------------------------------------------
extern "C" void kernel_launch(void* const* d_in, const int* in_sizes, int n_in,
                              void* d_out, int out_size)
{
    const float* x      = (const float*)d_in[0];
    const float* A_log  = (const float*)d_in[1];
    const float* W_B    = (const float*)d_in[2];
    const float* b_B    = (const float*)d_in[3];
    const float* W_C    = (const float*)d_in[4];
    const float* b_C    = (const float*)d_in[5];
    const float* W_dt   = (const float*)d_in[6];
    const float* b_dt   = (const float*)d_in[7];
    const float* D_skip = (const float*)d_in[8];
    const float* W_mix  = (const float*)d_in[9];
    const float* b_mix  = (const float*)d_in[10];
    const float* ln_g   = (const float*)d_in[11];
    const float* ln_b   = (const float*)d_in[12];
    const float* W_dec  = (const float*)d_in[13];
    const float* b_dec  = (const float*)d_in[14];
    float* out = (float*)d_out;

    float *p_h, *p_dt, *p_y;
    cudaGetSymbolAddress((void**)&p_h,  g_h);
    cudaGetSymbolAddress((void**)&p_dt, g_dt);
    cudaGetSymbolAddress((void**)&p_y,  g_y);

    cudaMemcpyAsync(p_h, x, sizeof(float) * BLD, cudaMemcpyDeviceToDevice);

    const dim3 gg(Dm / 128, (Bb * Ls) / 128);  // (4, 64)

    for (int i = 0; i < NL; i++) {
        // dt = softplus(h @ W_dt + b_dt)
        sgemm128<<<gg, 256>>>(p_h, W_dt + (size_t)i * Dm * Dm, b_dt + i * Dm,
                              p_dt, 1);
        // Bm, Cm
        bc_gemm<<<256, 256>>>(W_B + (size_t)i * Dm * Ns, b_B + i * Ns,
                              W_C + (size_t)i * Dm * Ns, b_C + i * Ns);
        // chunked associative scan + y (+ fused GELU)
        scan1<<<(Bb * Dm * (Cc - 1)) / 256, 256>>>(A_log, i);    // 248 blocks
        scan2<<<(BDN / 4) / 256, 256>>>();                       // 32 blocks
        scan3<<<(Bb * Dm * Cc) / 256, 256>>>(A_log, D_skip, i);  // 256 blocks
        // z = gelu(y) @ W_mix + b_mix
        sgemm128<<<gg, 256>>>(p_y, W_mix + (size_t)i * Dm * Dm, b_mix + i * Dm,
                              p_dt, 0);
        // h = h + LN(z)*g + b
        ln_res<<<(Bb * Ls * 32) / 256, 256>>>(ln_g, ln_b, i);
    }

    // out = h @ W_dec + b_dec
    sgemm128<<<gg, 256>>>(p_h, W_dec, b_dec, out, 0);
}